// round 11
// baseline (speedup 1.0000x reference)
#include <cuda_runtime.h>
#include <cuda_fp16.h>
#include <cmath>
#include <cstdint>

#define L_SEQ  32768
#define DM     256
#define DH     256
#define NW1    512
#define CHUNK  32
#define NCHUNK (L_SEQ / CHUNK)   // 1024
#define NPOW   10                // lamPow[s] = lambda^(CHUNK * 2^s), s=0..9

// ---------------- scratch ----------------
// Channel-interleaved layout: col 2h = re_h, col 2h+1 = im_h.
__device__ __half  g_BuH[(size_t)L_SEQ * NW1];    // GEMM1 out (fp16), scan input
__device__ __half  g_xf[(size_t)L_SEQ * DM];      // x in fp16
__device__ __half  g_hf[(size_t)L_SEQ * NW1];     // h in fp16 (scan output)
__device__ __half  g_W1f[NW1 * DM];               // [512][256]
__device__ __half  g_W2f[DM * NW1];               // [256][512]
__device__ float2  g_lam[DH];
__device__ float2  g_lamPow[NPOW * DH];
__device__ float   g_carryf[(size_t)NCHUNK * NW1];
__device__ float   g_hinitf[(size_t)NCHUNK * NW1];

// ---------------- PTX helpers ----------------
__device__ __forceinline__ uint32_t smem_u32(const void* p) {
    uint32_t a;
    asm("{ .reg .u64 t; cvta.to.shared.u64 t, %1; cvt.u32.u64 %0, t; }" : "=r"(a) : "l"(p));
    return a;
}
__device__ __forceinline__ void cp16(uint32_t s, const void* g) {
    asm volatile("cp.async.cg.shared.global [%0], [%1], 16;" :: "r"(s), "l"(g));
}
__device__ __forceinline__ void cp_commit() {
    asm volatile("cp.async.commit_group;" ::: "memory");
}
__device__ __forceinline__ void ldsm4(uint32_t addr, uint32_t* r) {
    asm volatile("ldmatrix.sync.aligned.m8n8.x4.shared.b16 {%0,%1,%2,%3}, [%4];"
                 : "=r"(r[0]), "=r"(r[1]), "=r"(r[2]), "=r"(r[3]) : "r"(addr));
}
__device__ __forceinline__ void mma_f16(float* c, const uint32_t* a, const uint32_t* b) {
    asm volatile("mma.sync.aligned.m16n8k16.row.col.f32.f16.f16.f32 "
                 "{%0,%1,%2,%3},{%4,%5,%6,%7},{%8,%9},{%0,%1,%2,%3};"
                 : "+f"(c[0]), "+f"(c[1]), "+f"(c[2]), "+f"(c[3])
                 : "r"(a[0]), "r"(a[1]), "r"(a[2]), "r"(a[3]), "r"(b[0]), "r"(b[1]));
}

// ---------------- setup (params + weights merged) ----------------
__global__ void setup_all(const float* __restrict__ nu_log,
                          const float* __restrict__ theta_log,
                          const float* __restrict__ gamma_log,
                          const float* __restrict__ B_re,
                          const float* __restrict__ B_im,
                          const float* __restrict__ C_re,
                          const float* __restrict__ C_im) {
    int n = blockIdx.x;   // 0..511 : channel-interleaved (2h=re, 2h+1=im)
    int t = threadIdx.x;  // 0..255
    int h = n >> 1;
    int im = n & 1;
    float g = expf(gamma_log[h]);
    float w = (im ? B_im[h * DM + t] : B_re[h * DM + t]) * g;
    g_W1f[n * DM + t] = __float2half(w);
    float c2 = im ? -C_im[t * DH + h] : C_re[t * DH + h];
    g_W2f[t * NW1 + n] = __float2half(c2);
    if (n == 0) {   // block 0: lambda params (t = channel)
        double nu = exp((double)nu_log[t]);
        double th = exp((double)theta_log[t]);
        double r  = exp(-nu);
        g_lam[t]  = make_float2((float)(r * cos(th)), (float)(r * sin(th)));
        #pragma unroll
        for (int s = 0; s < NPOW; s++) {
            double sc = (double)CHUNK * (double)(1 << s);
            double rr = exp(-sc * nu);
            double aa = sc * th;
            g_lamPow[s * DH + t] = make_float2((float)(rr * cos(aa)), (float)(rr * sin(aa)));
        }
    }
}

__global__ void cvt_x(const float* __restrict__ x) {
    size_t i = (size_t)blockIdx.x * 256 + threadIdx.x;   // float4 index
    float4 v = ((const float4*)x)[i];
    __half2 p0 = __floats2half2_rn(v.x, v.y);
    __half2 p1 = __floats2half2_rn(v.z, v.w);
    uint2 u;
    u.x = *reinterpret_cast<uint32_t*>(&p0);
    u.y = *reinterpret_cast<uint32_t*>(&p1);
    *reinterpret_cast<uint2*>(g_xf + i * 4) = u;
}

// ---------------- fp16 mma.sync GEMM (single term, KC=64, 3-stage) -----------
#define KC      64
#define PITCH   144                        // 128B data + 16B pad (4-bank row shift)
#define TILE_B  (128 * PITCH)              // 18432
#define NSTAGE  3
#define STAGE_B (2 * TILE_B)               // 36864
#define SMEM_G  (NSTAGE * STAGE_B)         // 110592 (108 KB; 2 CTA/SM = 216 KB)
#define O_A 0
#define O_B TILE_B
#define SP_H 272                           // fp16 stash pitch (4-bank row shift)

template<int KTOT, int NGLOB, bool EPI, bool FUSE_SCAN, bool HALF_OUT>
__device__ __forceinline__ void mm_gemm_body(
    const __half* __restrict__ A, const __half* __restrict__ B,
    void* __restrict__ Cm, const float* __restrict__ X, const float* __restrict__ Dv)
{
    extern __shared__ char smem[];
    const uint32_t sb = smem_u32(smem);
    const int tid = threadIdx.x, wid = tid >> 5, l = tid & 31;
    const int rowbase = blockIdx.y * 128;
    const int colbase = blockIdx.x * 128;
    const int wm = wid & 3, wn = wid >> 2;

    float acc[2][8][4];
    #pragma unroll
    for (int i = 0; i < 2; i++)
        #pragma unroll
        for (int j = 0; j < 8; j++)
            #pragma unroll
            for (int q = 0; q < 4; q++) acc[i][j][q] = 0.f;

    const int srow  = tid >> 1;            // 0..127
    const int shalf = tid & 1;             // 64B half of the 128B row

    auto load_stage = [&](int c) {
        const uint32_t base = sb + (c % NSTAGE) * STAGE_B;
        const int k0 = c * KC;
        const __half* gA = A + (size_t)(rowbase + srow) * KTOT + k0 + shalf * 32;
        const __half* gB = B + (size_t)(colbase + srow) * KTOT + k0 + shalf * 32;
        uint32_t so = srow * PITCH + shalf * 64;
        #pragma unroll
        for (int d = 0; d < 4; d++) {
            cp16(base + O_A + so + d * 16, gA + d * 8);
            cp16(base + O_B + so + d * 16, gB + d * 8);
        }
    };

    auto compute = [&](int c) {
        const uint32_t base = sb + (c % NSTAGE) * STAGE_B;
        #pragma unroll
        for (int kk = 0; kk < KC / 16; kk++) {
            const int k16 = kk * 16;
            uint32_t av[2][4], bv[4][4];
            const uint32_t arow_off =
                (uint32_t)(wm * 32 + (l & 15)) * PITCH + (uint32_t)(k16 + ((l >> 4) << 3)) * 2;
            const int g = l >> 3;
            const int nadd = ((g & 2) << 2) + (l & 7);
            const int kadd = k16 + ((g & 1) << 3);
            #pragma unroll
            for (int mt = 0; mt < 2; mt++)
                ldsm4(base + O_A + arow_off + (uint32_t)(mt * 16) * PITCH, av[mt]);
            #pragma unroll
            for (int p = 0; p < 4; p++)
                ldsm4(base + O_B + (uint32_t)(wn * 64 + p * 16 + nadd) * PITCH
                           + (uint32_t)kadd * 2, bv[p]);
            #pragma unroll
            for (int mt = 0; mt < 2; mt++)
                #pragma unroll
                for (int nt = 0; nt < 8; nt++)
                    mma_f16(acc[mt][nt], av[mt], &bv[nt >> 1][(nt & 1) * 2]);
        }
    };

    const int NCH = KTOT / KC;
    #pragma unroll
    for (int s = 0; s < NSTAGE - 1; s++) { load_stage(s); cp_commit(); }
    for (int c = 0; c < NCH; c++) {
        if (c + NSTAGE - 1 < NCH) load_stage(c + NSTAGE - 1);
        cp_commit();                       // (possibly empty) keeps group counts uniform
        asm volatile("cp.async.wait_group %0;" :: "n"(NSTAGE - 1) : "memory");
        __syncthreads();
        compute(c);
        __syncthreads();
    }
    // smem pipeline fully consumed past this point

    const int erow = (l >> 2);
    const int ecol = (l & 3) * 2;
    #pragma unroll
    for (int mt = 0; mt < 2; mt++) {
        #pragma unroll
        for (int nt = 0; nt < 8; nt++) {
            int rl = wm * 32 + mt * 16 + erow;        // CTA-local row
            int cl = wn * 64 + nt * 8 + ecol;         // CTA-local col (even)
            int r0 = rowbase + rl;
            int c0 = colbase + cl;
            float2 v0 = make_float2(acc[mt][nt][0], acc[mt][nt][1]);
            float2 v1 = make_float2(acc[mt][nt][2], acc[mt][nt][3]);
            if (EPI) {
                float2 x0 = *(const float2*)&X[(size_t)r0 * DM + c0];
                float2 x1 = *(const float2*)&X[(size_t)(r0 + 8) * DM + c0];
                float2 dv = *(const float2*)&Dv[c0];
                v0.x = fmaf(x0.x, dv.x, v0.x); v0.y = fmaf(x0.y, dv.y, v0.y);
                v1.x = fmaf(x1.x, dv.x, v1.x); v1.y = fmaf(x1.y, dv.y, v1.y);
            }
            if (HALF_OUT) {
                __half2 q0 = __floats2half2_rn(v0.x, v0.y);
                __half2 q1 = __floats2half2_rn(v1.x, v1.y);
                __half* C = (__half*)Cm;
                *(__half2*)&C[(size_t)r0 * NGLOB + c0]       = q0;
                *(__half2*)&C[(size_t)(r0 + 8) * NGLOB + c0] = q1;
                if (FUSE_SCAN) {   // conflict-free stash (272B pitch)
                    *(uint32_t*)(smem + rl * SP_H + cl * 2)       = *(uint32_t*)&q0;
                    *(uint32_t*)(smem + (rl + 8) * SP_H + cl * 2) = *(uint32_t*)&q1;
                }
            } else {
                float* C = (float*)Cm;
                *(float2*)&C[(size_t)r0 * NGLOB + c0]       = v0;
                *(float2*)&C[(size_t)(r0 + 8) * NGLOB + c0] = v1;
            }
        }
    }

    if (FUSE_SCAN) {
        __syncthreads();
        // 4 sub-chunks of 32 rows x 64 complex channels -> 256 independent scans
        int ch = tid & 63;          // CTA-local complex channel (0..63)
        int ck = tid >> 6;          // sub-chunk (0..3): rows [32ck, 32ck+32)
        float2 lam = g_lam[(colbase >> 1) + ch];
        float hr = 0.f, hi = 0.f;
        const char* sp = smem + ck * 32 * SP_H + ch * 4;
        #pragma unroll 8
        for (int t = 0; t < CHUNK; t++) {
            uint32_t u = *(const uint32_t*)(sp + t * SP_H);
            __half2 hv = *(__half2*)&u;
            float br = __low2float(hv), bi = __high2float(hv);
            float nr = fmaf(lam.x, hr, fmaf(-lam.y, hi, br));
            float ni = fmaf(lam.x, hi, fmaf( lam.y, hr, bi));
            hr = nr; hi = ni;
        }
        int chunk = blockIdx.y * 4 + ck;
        *(float2*)&g_carryf[(size_t)chunk * NW1 + colbase + 2 * ch] =
            make_float2(hr, hi);
    }
}

// Wrappers: bind __device__ globals from DEVICE code only.
__global__ void __launch_bounds__(256, 2) gemm1_k() {
    mm_gemm_body<DM, NW1, false, true, true>(g_xf, g_W1f, g_BuH, nullptr, nullptr);
}
__global__ void __launch_bounds__(256, 2) gemm2_k(float* __restrict__ y,
                                                  const float* __restrict__ X,
                                                  const float* __restrict__ Dv) {
    mm_gemm_body<NW1, DM, true, false, false>(g_hf, g_W2f, y, X, Dv);
}

// ---------------- chunk prefix: warp-shuffle scan (no __syncthreads) ---------
// One warp per channel pair j (float4 = 2 complex channels).
// Lane t serially scans chunks [32t, 32t+32) (multiplier lamT = lambda^32),
// 5-stage shuffle KS across lanes (multipliers lambda^(1024*2^s) = lamPow[5+s]),
// then re-emits exclusive prefixes.
__global__ void __launch_bounds__(256) chunk_prefix_warp() {
    int j    = blockIdx.x * 8 + (threadIdx.x >> 5);   // 0..127
    int lane = threadIdx.x & 31;
    float2 lt0 = g_lamPow[2 * j],     lt1 = g_lamPow[2 * j + 1];   // lamT (s=0)
    const float4* carry = (const float4*)g_carryf;
    float4* hinit = (float4*)g_hinitf;

    // local inclusive scan of my 32 chunks
    float4 b = make_float4(0.f, 0.f, 0.f, 0.f);
    #pragma unroll 4
    for (int t = 0; t < 32; t++) {
        float4 cv = carry[(size_t)(lane * 32 + t) * 128 + j];
        float nr0 = fmaf(lt0.x, b.x, fmaf(-lt0.y, b.y, cv.x));
        float ni0 = fmaf(lt0.x, b.y, fmaf( lt0.y, b.x, cv.y));
        float nr1 = fmaf(lt1.x, b.z, fmaf(-lt1.y, b.w, cv.z));
        float ni1 = fmaf(lt1.x, b.w, fmaf( lt1.y, b.z, cv.w));
        b = make_float4(nr0, ni0, nr1, ni1);
    }
    // KS across lanes
    #pragma unroll
    for (int s = 0; s < 5; s++) {
        int d = 1 << s;
        float4 up;
        up.x = __shfl_up_sync(0xffffffffu, b.x, d);
        up.y = __shfl_up_sync(0xffffffffu, b.y, d);
        up.z = __shfl_up_sync(0xffffffffu, b.z, d);
        up.w = __shfl_up_sync(0xffffffffu, b.w, d);
        float2 p0 = g_lamPow[(5 + s) * DH + 2 * j];
        float2 p1 = g_lamPow[(5 + s) * DH + 2 * j + 1];
        if (lane >= d) {
            b.x += p0.x * up.x - p0.y * up.y;
            b.y += p0.x * up.y + p0.y * up.x;
            b.z += p1.x * up.z - p1.y * up.w;
            b.w += p1.x * up.w + p1.y * up.z;
        }
    }
    // exclusive across lanes
    float4 ex;
    ex.x = __shfl_up_sync(0xffffffffu, b.x, 1);
    ex.y = __shfl_up_sync(0xffffffffu, b.y, 1);
    ex.z = __shfl_up_sync(0xffffffffu, b.z, 1);
    ex.w = __shfl_up_sync(0xffffffffu, b.w, 1);
    if (lane == 0) ex = make_float4(0.f, 0.f, 0.f, 0.f);
    // emit hinit for my 32 chunks
    #pragma unroll 4
    for (int t = 0; t < 32; t++) {
        size_t idx = (size_t)(lane * 32 + t) * 128 + j;
        hinit[idx] = ex;
        float4 cv = carry[idx];
        float nr0 = fmaf(lt0.x, ex.x, fmaf(-lt0.y, ex.y, cv.x));
        float ni0 = fmaf(lt0.x, ex.y, fmaf( lt0.y, ex.x, cv.y));
        float nr1 = fmaf(lt1.x, ex.z, fmaf(-lt1.y, ex.w, cv.z));
        float ni1 = fmaf(lt1.x, ex.w, fmaf( lt1.y, ex.z, cv.w));
        ex = make_float4(nr0, ni0, nr1, ni1);
    }
}

// ---------------- scan_apply: fp16 Bu -> fp16 h ------------------------------
__global__ void scan_apply() {
    int c = blockIdx.x, j = threadIdx.x;   // j: 0..127, 2 complex channels each
    float2 l0 = g_lam[2 * j], l1 = g_lam[2 * j + 1];
    float4 h = ((const float4*)g_hinitf)[(size_t)c * 128 + j];
    const uint2* base = (const uint2*)(g_BuH + (size_t)c * CHUNK * NW1) + j;
    __half* of = g_hf + (size_t)c * CHUNK * NW1 + 4 * j;
    #pragma unroll 8
    for (int t = 0; t < CHUNK; t++) {
        uint2 u = base[(size_t)t * 128];
        __half2 b0 = *(__half2*)&u.x;
        __half2 b1 = *(__half2*)&u.y;
        float nr0 = fmaf(l0.x, h.x, fmaf(-l0.y, h.y, __low2float(b0)));
        float ni0 = fmaf(l0.x, h.y, fmaf( l0.y, h.x, __high2float(b0)));
        float nr1 = fmaf(l1.x, h.z, fmaf(-l1.y, h.w, __low2float(b1)));
        float ni1 = fmaf(l1.x, h.w, fmaf( l1.y, h.z, __high2float(b1)));
        h = make_float4(nr0, ni0, nr1, ni1);
        __half2 p0 = __floats2half2_rn(nr0, ni0);
        __half2 p1 = __floats2half2_rn(nr1, ni1);
        uint2 o;
        o.x = *reinterpret_cast<uint32_t*>(&p0);
        o.y = *reinterpret_cast<uint32_t*>(&p1);
        *reinterpret_cast<uint2*>(of + (size_t)t * NW1) = o;
    }
}

// ---------------- entry ----------------
extern "C" void kernel_launch(void* const* d_in, const int* in_sizes, int n_in,
                              void* d_out, int out_size) {
    const float* x         = (const float*)d_in[0];
    const float* nu_log    = (const float*)d_in[1];
    const float* theta_log = (const float*)d_in[2];
    const float* gamma_log = (const float*)d_in[3];
    const float* B_re      = (const float*)d_in[4];
    const float* B_im      = (const float*)d_in[5];
    const float* C_re      = (const float*)d_in[6];
    const float* C_im      = (const float*)d_in[7];
    const float* Dv        = (const float*)d_in[8];
    float* y = (float*)d_out;

    cudaFuncSetAttribute(gemm1_k, cudaFuncAttributeMaxDynamicSharedMemorySize, SMEM_G);
    cudaFuncSetAttribute(gemm2_k, cudaFuncAttributeMaxDynamicSharedMemorySize, SMEM_G);

    setup_all<<<512, 256>>>(nu_log, theta_log, gamma_log, B_re, B_im, C_re, C_im);
    cvt_x<<<(L_SEQ * DM / 4) / 256, 256>>>(x);

    // GEMM1 (+ fused per-chunk carry scan): BuH = x @ W1T^T
    gemm1_k<<<dim3(NW1 / 128, L_SEQ / 128), 256, SMEM_G>>>();

    chunk_prefix_warp<<<16, 256>>>();
    scan_apply<<<NCHUNK, 128>>>();

    // GEMM2: y = h @ W2T^T + x*D
    gemm2_k<<<dim3(DM / 128, L_SEQ / 128), 256, SMEM_G>>>(y, x, Dv);
}

// round 12
// speedup vs baseline: 1.1682x; 1.1682x over previous
#include <cuda_runtime.h>
#include <cuda_fp16.h>
#include <cmath>
#include <cstdint>

#define L_SEQ  32768
#define DM     256
#define DH     256
#define NW1    512
#define CHUNK  32
#define NCHUNK (L_SEQ / CHUNK)   // 1024
#define NPOW   10                // lamPow[s] = lambda^(CHUNK * 2^s), s=0..9

// ---------------- scratch ----------------
// Channel-interleaved layout: col 2h = re_h, col 2h+1 = im_h.
__device__ __half  g_BuH[(size_t)L_SEQ * NW1];    // GEMM1 out (fp16), scan input
__device__ __half  g_xf[(size_t)L_SEQ * DM];      // x in fp16
__device__ __half  g_hf[(size_t)L_SEQ * NW1];     // h in fp16 (scan output)
__device__ __half  g_W1f[NW1 * DM];               // [512][256]
__device__ __half  g_W2f[DM * NW1];               // [256][512]
__device__ float2  g_lam[DH];
__device__ float2  g_lamPow[NPOW * DH];
__device__ float   g_carryf[(size_t)NCHUNK * NW1];
__device__ float   g_hinitf[(size_t)NCHUNK * NW1];

// ---------------- PTX helpers ----------------
__device__ __forceinline__ uint32_t smem_u32(const void* p) {
    uint32_t a;
    asm("{ .reg .u64 t; cvta.to.shared.u64 t, %1; cvt.u32.u64 %0, t; }" : "=r"(a) : "l"(p));
    return a;
}
__device__ __forceinline__ void cp16(uint32_t s, const void* g) {
    asm volatile("cp.async.cg.shared.global [%0], [%1], 16;" :: "r"(s), "l"(g));
}
__device__ __forceinline__ void cp_commit() {
    asm volatile("cp.async.commit_group;" ::: "memory");
}
__device__ __forceinline__ void ldsm4(uint32_t addr, uint32_t* r) {
    asm volatile("ldmatrix.sync.aligned.m8n8.x4.shared.b16 {%0,%1,%2,%3}, [%4];"
                 : "=r"(r[0]), "=r"(r[1]), "=r"(r[2]), "=r"(r[3]) : "r"(addr));
}
__device__ __forceinline__ void mma_f16(float* c, const uint32_t* a, const uint32_t* b) {
    asm volatile("mma.sync.aligned.m16n8k16.row.col.f32.f16.f16.f32 "
                 "{%0,%1,%2,%3},{%4,%5,%6,%7},{%8,%9},{%0,%1,%2,%3};"
                 : "+f"(c[0]), "+f"(c[1]), "+f"(c[2]), "+f"(c[3])
                 : "r"(a[0]), "r"(a[1]), "r"(a[2]), "r"(a[3]), "r"(b[0]), "r"(b[1]));
}

// ---------------- setup (params + weights merged) ----------------
__global__ void setup_all(const float* __restrict__ nu_log,
                          const float* __restrict__ theta_log,
                          const float* __restrict__ gamma_log,
                          const float* __restrict__ B_re,
                          const float* __restrict__ B_im,
                          const float* __restrict__ C_re,
                          const float* __restrict__ C_im) {
    int n = blockIdx.x;   // 0..511 : channel-interleaved (2h=re, 2h+1=im)
    int t = threadIdx.x;  // 0..255
    int h = n >> 1;
    int im = n & 1;
    float g = expf(gamma_log[h]);
    float w = (im ? B_im[h * DM + t] : B_re[h * DM + t]) * g;
    g_W1f[n * DM + t] = __float2half(w);
    float c2 = im ? -C_im[t * DH + h] : C_re[t * DH + h];
    g_W2f[t * NW1 + n] = __float2half(c2);
    if (n == 0) {   // block 0: lambda params (t = channel)
        double nu = exp((double)nu_log[t]);
        double th = exp((double)theta_log[t]);
        double r  = exp(-nu);
        g_lam[t]  = make_float2((float)(r * cos(th)), (float)(r * sin(th)));
        #pragma unroll
        for (int s = 0; s < NPOW; s++) {
            double sc = (double)CHUNK * (double)(1 << s);
            double rr = exp(-sc * nu);
            double aa = sc * th;
            g_lamPow[s * DH + t] = make_float2((float)(rr * cos(aa)), (float)(rr * sin(aa)));
        }
    }
}

__global__ void cvt_x(const float* __restrict__ x) {
    size_t i = (size_t)blockIdx.x * 256 + threadIdx.x;   // float4 index
    float4 v = ((const float4*)x)[i];
    __half2 p0 = __floats2half2_rn(v.x, v.y);
    __half2 p1 = __floats2half2_rn(v.z, v.w);
    uint2 u;
    u.x = *reinterpret_cast<uint32_t*>(&p0);
    u.y = *reinterpret_cast<uint32_t*>(&p1);
    *reinterpret_cast<uint2*>(g_xf + i * 4) = u;
}

// ---------------- fp16 mma.sync GEMM (KC=32, 4-stage, 1 sync/chunk) ----------
#define KC      32
#define PITCH   80
#define TILE_B  (128 * PITCH)              // 10240
#define NSTAGE  4
#define STAGE_B (2 * TILE_B)               // 20480
#define SMEM_G  (NSTAGE * STAGE_B)         // 81920 per CTA (x2 CTA/SM)
#define O_A 0
#define O_B TILE_B
#define SP_H 272                           // fp16 stash pitch (4-bank row shift)

template<int KTOT, int NGLOB, bool EPI, bool FUSE_SCAN, bool HALF_OUT>
__device__ __forceinline__ void mm_gemm_body(
    const __half* __restrict__ A, const __half* __restrict__ B,
    void* __restrict__ Cm, const float* __restrict__ X, const float* __restrict__ Dv)
{
    extern __shared__ char smem[];
    const uint32_t sb = smem_u32(smem);
    const int tid = threadIdx.x, wid = tid >> 5, l = tid & 31;
    const int rowbase = blockIdx.y * 128;
    const int colbase = blockIdx.x * 128;
    const int wm = wid & 3, wn = wid >> 2;

    float acc[2][8][4];
    #pragma unroll
    for (int i = 0; i < 2; i++)
        #pragma unroll
        for (int j = 0; j < 8; j++)
            #pragma unroll
            for (int q = 0; q < 4; q++) acc[i][j][q] = 0.f;

    const int srow = tid >> 1;
    const int sq   = (tid & 1) * 2;

    auto load_stage = [&](int c) {
        const uint32_t base = sb + (c & (NSTAGE - 1)) * STAGE_B;
        const int k0 = c * KC;
        const __half* gA = A + (size_t)(rowbase + srow) * KTOT + k0;
        const __half* gB = B + (size_t)(colbase + srow) * KTOT + k0;
        #pragma unroll
        for (int d = 0; d < 2; d++) {
            int q = sq + d;
            uint32_t so = srow * PITCH + q * 16;
            cp16(base + O_A + so, gA + q * 8);
            cp16(base + O_B + so, gB + q * 8);
        }
    };

    auto compute = [&](int c) {
        const uint32_t base = sb + (c & (NSTAGE - 1)) * STAGE_B;
        #pragma unroll
        for (int kk = 0; kk < 2; kk++) {
            const int k16 = kk * 16;
            uint32_t av[2][4], bv[4][4];
            const uint32_t arow_off =
                (uint32_t)(wm * 32 + (l & 15)) * PITCH + (uint32_t)(k16 + ((l >> 4) << 3)) * 2;
            const int g = l >> 3;
            const int nadd = ((g & 2) << 2) + (l & 7);
            const int kadd = k16 + ((g & 1) << 3);
            #pragma unroll
            for (int mt = 0; mt < 2; mt++)
                ldsm4(base + O_A + arow_off + (uint32_t)(mt * 16) * PITCH, av[mt]);
            #pragma unroll
            for (int p = 0; p < 4; p++)
                ldsm4(base + O_B + (uint32_t)(wn * 64 + p * 16 + nadd) * PITCH
                           + (uint32_t)kadd * 2, bv[p]);
            #pragma unroll
            for (int mt = 0; mt < 2; mt++)
                #pragma unroll
                for (int nt = 0; nt < 8; nt++)
                    mma_f16(acc[mt][nt], av[mt], &bv[nt >> 1][(nt & 1) * 2]);
        }
    };

    // Single __syncthreads per chunk: wait -> sync -> compute -> load next.
    // load(c+3) overwrites buffer (c-1)&3; every thread issuing it has passed
    // the iteration-c barrier => all threads finished compute(c-1). Safe.
    const int NCH = KTOT / KC;
    #pragma unroll
    for (int s = 0; s < NSTAGE - 1; s++) { load_stage(s); cp_commit(); }
    for (int c = 0; c < NCH; c++) {
        asm volatile("cp.async.wait_group %0;" :: "n"(NSTAGE - 2) : "memory");
        __syncthreads();
        compute(c);
        if (c + NSTAGE - 1 < NCH) load_stage(c + NSTAGE - 1);
        cp_commit();                       // (possibly empty) keeps group counts uniform
    }

    const int erow = (l >> 2);
    const int ecol = (l & 3) * 2;
    #pragma unroll
    for (int mt = 0; mt < 2; mt++) {
        #pragma unroll
        for (int nt = 0; nt < 8; nt++) {
            int rl = wm * 32 + mt * 16 + erow;        // CTA-local row
            int cl = wn * 64 + nt * 8 + ecol;         // CTA-local col (even)
            int r0 = rowbase + rl;
            int c0 = colbase + cl;
            float2 v0 = make_float2(acc[mt][nt][0], acc[mt][nt][1]);
            float2 v1 = make_float2(acc[mt][nt][2], acc[mt][nt][3]);
            if (EPI) {
                float2 x0 = *(const float2*)&X[(size_t)r0 * DM + c0];
                float2 x1 = *(const float2*)&X[(size_t)(r0 + 8) * DM + c0];
                float2 dv = *(const float2*)&Dv[c0];
                v0.x = fmaf(x0.x, dv.x, v0.x); v0.y = fmaf(x0.y, dv.y, v0.y);
                v1.x = fmaf(x1.x, dv.x, v1.x); v1.y = fmaf(x1.y, dv.y, v1.y);
            }
            if (HALF_OUT) {
                __half2 q0 = __floats2half2_rn(v0.x, v0.y);
                __half2 q1 = __floats2half2_rn(v1.x, v1.y);
                __half* C = (__half*)Cm;
                *(__half2*)&C[(size_t)r0 * NGLOB + c0]       = q0;
                *(__half2*)&C[(size_t)(r0 + 8) * NGLOB + c0] = q1;
                if (FUSE_SCAN) {   // conflict-free stash (272B pitch, buffers 0-1 only)
                    *(uint32_t*)(smem + rl * SP_H + cl * 2)       = *(uint32_t*)&q0;
                    *(uint32_t*)(smem + (rl + 8) * SP_H + cl * 2) = *(uint32_t*)&q1;
                }
            } else {
                float* C = (float*)Cm;
                *(float2*)&C[(size_t)r0 * NGLOB + c0]       = v0;
                *(float2*)&C[(size_t)(r0 + 8) * NGLOB + c0] = v1;
            }
        }
    }

    if (FUSE_SCAN) {
        __syncthreads();
        // 4 sub-chunks of 32 rows x 64 complex channels -> 256 independent scans
        int ch = tid & 63;          // CTA-local complex channel (0..63)
        int ck = tid >> 6;          // sub-chunk (0..3): rows [32ck, 32ck+32)
        float2 lam = g_lam[(colbase >> 1) + ch];
        float hr = 0.f, hi = 0.f;
        const char* sp = smem + ck * 32 * SP_H + ch * 4;
        #pragma unroll 8
        for (int t = 0; t < CHUNK; t++) {
            uint32_t u = *(const uint32_t*)(sp + t * SP_H);
            __half2 hv = *(__half2*)&u;
            float br = __low2float(hv), bi = __high2float(hv);
            float nr = fmaf(lam.x, hr, fmaf(-lam.y, hi, br));
            float ni = fmaf(lam.x, hi, fmaf( lam.y, hr, bi));
            hr = nr; hi = ni;
        }
        int chunk = blockIdx.y * 4 + ck;
        *(float2*)&g_carryf[(size_t)chunk * NW1 + colbase + 2 * ch] =
            make_float2(hr, hi);
    }
}

// Wrappers: bind __device__ globals from DEVICE code only.
__global__ void __launch_bounds__(256, 2) gemm1_k() {
    mm_gemm_body<DM, NW1, false, true, true>(g_xf, g_W1f, g_BuH, nullptr, nullptr);
}
__global__ void __launch_bounds__(256, 2) gemm2_k(float* __restrict__ y,
                                                  const float* __restrict__ X,
                                                  const float* __restrict__ Dv) {
    mm_gemm_body<NW1, DM, true, false, false>(g_hf, g_W2f, y, X, Dv);
}

// ---------------- chunk prefix (block Kogge-Stone over 1024 chunks) ----------
__global__ void __launch_bounds__(NCHUNK) chunk_prefix_ks() {
    __shared__ float4 sm[NCHUNK];
    int c = threadIdx.x, j = blockIdx.x;   // j: channel pair 0..127
    float4 x = ((const float4*)g_carryf)[(size_t)c * 128 + j];
    sm[c] = x;
    __syncthreads();
    #pragma unroll
    for (int s = 0; s < NPOW; s++) {
        int d = 1 << s;
        float4 pv = make_float4(0.f, 0.f, 0.f, 0.f);
        if (c >= d) pv = sm[c - d];
        float2 p0 = g_lamPow[s * DH + 2 * j];
        float2 p1 = g_lamPow[s * DH + 2 * j + 1];
        __syncthreads();
        if (c >= d) {
            x.x += p0.x * pv.x - p0.y * pv.y;
            x.y += p0.x * pv.y + p0.y * pv.x;
            x.z += p1.x * pv.z - p1.y * pv.w;
            x.w += p1.x * pv.w + p1.y * pv.z;
        }
        sm[c] = x;
        __syncthreads();
    }
    float4 out = make_float4(0.f, 0.f, 0.f, 0.f);
    if (c > 0) out = sm[c - 1];
    ((float4*)g_hinitf)[(size_t)c * 128 + j] = out;
}

// ---------------- scan_apply: fp16 Bu -> fp16 h ------------------------------
__global__ void scan_apply() {
    int c = blockIdx.x, j = threadIdx.x;   // j: 0..127, 2 complex channels each
    float2 l0 = g_lam[2 * j], l1 = g_lam[2 * j + 1];
    float4 h = ((const float4*)g_hinitf)[(size_t)c * 128 + j];
    const uint2* base = (const uint2*)(g_BuH + (size_t)c * CHUNK * NW1) + j;
    __half* of = g_hf + (size_t)c * CHUNK * NW1 + 4 * j;
    #pragma unroll 8
    for (int t = 0; t < CHUNK; t++) {
        uint2 u = base[(size_t)t * 128];
        __half2 b0 = *(__half2*)&u.x;
        __half2 b1 = *(__half2*)&u.y;
        float nr0 = fmaf(l0.x, h.x, fmaf(-l0.y, h.y, __low2float(b0)));
        float ni0 = fmaf(l0.x, h.y, fmaf( l0.y, h.x, __high2float(b0)));
        float nr1 = fmaf(l1.x, h.z, fmaf(-l1.y, h.w, __low2float(b1)));
        float ni1 = fmaf(l1.x, h.w, fmaf( l1.y, h.z, __high2float(b1)));
        h = make_float4(nr0, ni0, nr1, ni1);
        __half2 p0 = __floats2half2_rn(nr0, ni0);
        __half2 p1 = __floats2half2_rn(nr1, ni1);
        uint2 o;
        o.x = *reinterpret_cast<uint32_t*>(&p0);
        o.y = *reinterpret_cast<uint32_t*>(&p1);
        *reinterpret_cast<uint2*>(of + (size_t)t * NW1) = o;
    }
}

// ---------------- entry ----------------
extern "C" void kernel_launch(void* const* d_in, const int* in_sizes, int n_in,
                              void* d_out, int out_size) {
    const float* x         = (const float*)d_in[0];
    const float* nu_log    = (const float*)d_in[1];
    const float* theta_log = (const float*)d_in[2];
    const float* gamma_log = (const float*)d_in[3];
    const float* B_re      = (const float*)d_in[4];
    const float* B_im      = (const float*)d_in[5];
    const float* C_re      = (const float*)d_in[6];
    const float* C_im      = (const float*)d_in[7];
    const float* Dv        = (const float*)d_in[8];
    float* y = (float*)d_out;

    cudaFuncSetAttribute(gemm1_k, cudaFuncAttributeMaxDynamicSharedMemorySize, SMEM_G);
    cudaFuncSetAttribute(gemm2_k, cudaFuncAttributeMaxDynamicSharedMemorySize, SMEM_G);

    setup_all<<<512, 256>>>(nu_log, theta_log, gamma_log, B_re, B_im, C_re, C_im);
    cvt_x<<<(L_SEQ * DM / 4) / 256, 256>>>(x);

    // GEMM1 (+ fused per-chunk carry scan): BuH = x @ W1T^T
    gemm1_k<<<dim3(NW1 / 128, L_SEQ / 128), 256, SMEM_G>>>();

    chunk_prefix_ks<<<128, NCHUNK>>>();
    scan_apply<<<NCHUNK, 128>>>();

    // GEMM2: y = h @ W2T^T + x*D
    gemm2_k<<<dim3(DM / 128, L_SEQ / 128), 256, SMEM_G>>>(y, x, Dv);
}

// round 13
// speedup vs baseline: 1.2323x; 1.0548x over previous
#include <cuda_runtime.h>
#include <cuda_fp16.h>
#include <cmath>
#include <cstdint>

#define L_SEQ  32768
#define DM     256
#define DH     256
#define NW1    512
#define CHUNK  32
#define NCHUNK (L_SEQ / CHUNK)   // 1024
#define NPOW   10                // lamPow[s] = lambda^(CHUNK * 2^s), s=0..9

// ---------------- scratch ----------------
// Channel-interleaved layout: col 2h = re_h, col 2h+1 = im_h.
__device__ __half  g_BuH[(size_t)L_SEQ * NW1];    // GEMM1 out (fp16), scan input
__device__ __half  g_xf[(size_t)L_SEQ * DM];      // x in fp16
__device__ __half  g_hf[(size_t)L_SEQ * NW1];     // h in fp16 (scan output)
__device__ __half  g_W1f[NW1 * DM];               // [512][256]
__device__ __half  g_W2f[DM * NW1];               // [256][512]
__device__ float2  g_lam[DH];
__device__ float2  g_lamPow[NPOW * DH];
__device__ float   g_carryf[(size_t)NCHUNK * NW1];
__device__ float   g_hinitf[(size_t)NCHUNK * NW1];

// ---------------- PTX helpers ----------------
__device__ __forceinline__ uint32_t smem_u32(const void* p) {
    uint32_t a;
    asm("{ .reg .u64 t; cvta.to.shared.u64 t, %1; cvt.u32.u64 %0, t; }" : "=r"(a) : "l"(p));
    return a;
}
__device__ __forceinline__ void cp16(uint32_t s, const void* g) {
    asm volatile("cp.async.cg.shared.global [%0], [%1], 16;" :: "r"(s), "l"(g));
}
__device__ __forceinline__ void cp_commit() {
    asm volatile("cp.async.commit_group;" ::: "memory");
}
__device__ __forceinline__ void ldsm4(uint32_t addr, uint32_t* r) {
    asm volatile("ldmatrix.sync.aligned.m8n8.x4.shared.b16 {%0,%1,%2,%3}, [%4];"
                 : "=r"(r[0]), "=r"(r[1]), "=r"(r[2]), "=r"(r[3]) : "r"(addr));
}
__device__ __forceinline__ void mma_f16(float* c, const uint32_t* a, const uint32_t* b) {
    asm volatile("mma.sync.aligned.m16n8k16.row.col.f32.f16.f16.f32 "
                 "{%0,%1,%2,%3},{%4,%5,%6,%7},{%8,%9},{%0,%1,%2,%3};"
                 : "+f"(c[0]), "+f"(c[1]), "+f"(c[2]), "+f"(c[3])
                 : "r"(a[0]), "r"(a[1]), "r"(a[2]), "r"(a[3]), "r"(b[0]), "r"(b[1]));
}

// step both channels: out = lam * h + v   (complex per float2 half)
__device__ __forceinline__ float4 cstep(float2 l0, float2 l1, float4 h, float4 v) {
    float4 o;
    o.x = fmaf(l0.x, h.x, fmaf(-l0.y, h.y, v.x));
    o.y = fmaf(l0.x, h.y, fmaf( l0.y, h.x, v.y));
    o.z = fmaf(l1.x, h.z, fmaf(-l1.y, h.w, v.z));
    o.w = fmaf(l1.x, h.w, fmaf( l1.y, h.z, v.w));
    return o;
}
__device__ __forceinline__ float4 shfl_up4(float4 v, int d) {
    float4 o;
    o.x = __shfl_up_sync(0xffffffffu, v.x, d);
    o.y = __shfl_up_sync(0xffffffffu, v.y, d);
    o.z = __shfl_up_sync(0xffffffffu, v.z, d);
    o.w = __shfl_up_sync(0xffffffffu, v.w, d);
    return o;
}

// ---------------- setup (params + weights + x convert, one kernel) -----------
__global__ void setup_all(const float* __restrict__ nu_log,
                          const float* __restrict__ theta_log,
                          const float* __restrict__ gamma_log,
                          const float* __restrict__ B_re,
                          const float* __restrict__ B_im,
                          const float* __restrict__ C_re,
                          const float* __restrict__ C_im,
                          const float* __restrict__ x) {
    int blk = blockIdx.x;
    int t = threadIdx.x;  // 0..255
    if (blk < 512) {      // weights
        int n = blk;      // channel-interleaved (2h=re, 2h+1=im)
        int h = n >> 1;
        int im = n & 1;
        float g = expf(gamma_log[h]);
        float w = (im ? B_im[h * DM + t] : B_re[h * DM + t]) * g;
        g_W1f[n * DM + t] = __float2half(w);
        float c2 = im ? -C_im[t * DH + h] : C_re[t * DH + h];
        g_W2f[t * NW1 + n] = __float2half(c2);
        if (n == 0) {     // block 0: lambda params (t = channel)
            double nu = exp((double)nu_log[t]);
            double th = exp((double)theta_log[t]);
            double r  = exp(-nu);
            g_lam[t]  = make_float2((float)(r * cos(th)), (float)(r * sin(th)));
            #pragma unroll
            for (int s = 0; s < NPOW; s++) {
                double sc = (double)CHUNK * (double)(1 << s);
                double rr = exp(-sc * nu);
                double aa = sc * th;
                g_lamPow[s * DH + t] =
                    make_float2((float)(rr * cos(aa)), (float)(rr * sin(aa)));
            }
        }
    } else {              // x -> fp16
        size_t i = (size_t)(blk - 512) * 256 + t;   // float4 index
        float4 v = ((const float4*)x)[i];
        __half2 p0 = __floats2half2_rn(v.x, v.y);
        __half2 p1 = __floats2half2_rn(v.z, v.w);
        uint2 u;
        u.x = *reinterpret_cast<uint32_t*>(&p0);
        u.y = *reinterpret_cast<uint32_t*>(&p1);
        *reinterpret_cast<uint2*>(g_xf + i * 4) = u;
    }
}

// ---------------- fp16 mma.sync GEMM (KC=32, 4-stage, 1 sync/chunk) ----------
#define KC      32
#define PITCH   80
#define TILE_B  (128 * PITCH)              // 10240
#define NSTAGE  4
#define STAGE_B (2 * TILE_B)               // 20480
#define SMEM_G  (NSTAGE * STAGE_B)         // 81920 per CTA (x2 CTA/SM)
#define O_A 0
#define O_B TILE_B
#define SP_H 272                           // fp16 stash pitch (4-bank row shift)

template<int KTOT, int NGLOB, bool EPI, bool FUSE_SCAN, bool HALF_OUT>
__device__ __forceinline__ void mm_gemm_body(
    const __half* __restrict__ A, const __half* __restrict__ B,
    void* __restrict__ Cm, const float* __restrict__ X, const float* __restrict__ Dv)
{
    extern __shared__ char smem[];
    const uint32_t sb = smem_u32(smem);
    const int tid = threadIdx.x, wid = tid >> 5, l = tid & 31;
    const int rowbase = blockIdx.y * 128;
    const int colbase = blockIdx.x * 128;
    const int wm = wid & 3, wn = wid >> 2;

    float acc[2][8][4];
    #pragma unroll
    for (int i = 0; i < 2; i++)
        #pragma unroll
        for (int j = 0; j < 8; j++)
            #pragma unroll
            for (int q = 0; q < 4; q++) acc[i][j][q] = 0.f;

    const int srow = tid >> 1;
    const int sq   = (tid & 1) * 2;

    auto load_stage = [&](int c) {
        const uint32_t base = sb + (c & (NSTAGE - 1)) * STAGE_B;
        const int k0 = c * KC;
        const __half* gA = A + (size_t)(rowbase + srow) * KTOT + k0;
        const __half* gB = B + (size_t)(colbase + srow) * KTOT + k0;
        #pragma unroll
        for (int d = 0; d < 2; d++) {
            int q = sq + d;
            uint32_t so = srow * PITCH + q * 16;
            cp16(base + O_A + so, gA + q * 8);
            cp16(base + O_B + so, gB + q * 8);
        }
    };

    auto compute = [&](int c) {
        const uint32_t base = sb + (c & (NSTAGE - 1)) * STAGE_B;
        #pragma unroll
        for (int kk = 0; kk < 2; kk++) {
            const int k16 = kk * 16;
            uint32_t av[2][4], bv[4][4];
            const uint32_t arow_off =
                (uint32_t)(wm * 32 + (l & 15)) * PITCH + (uint32_t)(k16 + ((l >> 4) << 3)) * 2;
            const int g = l >> 3;
            const int nadd = ((g & 2) << 2) + (l & 7);
            const int kadd = k16 + ((g & 1) << 3);
            #pragma unroll
            for (int mt = 0; mt < 2; mt++)
                ldsm4(base + O_A + arow_off + (uint32_t)(mt * 16) * PITCH, av[mt]);
            #pragma unroll
            for (int p = 0; p < 4; p++)
                ldsm4(base + O_B + (uint32_t)(wn * 64 + p * 16 + nadd) * PITCH
                           + (uint32_t)kadd * 2, bv[p]);
            #pragma unroll
            for (int mt = 0; mt < 2; mt++)
                #pragma unroll
                for (int nt = 0; nt < 8; nt++)
                    mma_f16(acc[mt][nt], av[mt], &bv[nt >> 1][(nt & 1) * 2]);
        }
    };

    // Single __syncthreads per chunk (safety argument: see round-12 comment).
    const int NCH = KTOT / KC;
    #pragma unroll
    for (int s = 0; s < NSTAGE - 1; s++) { load_stage(s); cp_commit(); }
    for (int c = 0; c < NCH; c++) {
        asm volatile("cp.async.wait_group %0;" :: "n"(NSTAGE - 2) : "memory");
        __syncthreads();
        compute(c);
        if (c + NSTAGE - 1 < NCH) load_stage(c + NSTAGE - 1);
        cp_commit();
    }

    const int erow = (l >> 2);
    const int ecol = (l & 3) * 2;
    #pragma unroll
    for (int mt = 0; mt < 2; mt++) {
        #pragma unroll
        for (int nt = 0; nt < 8; nt++) {
            int rl = wm * 32 + mt * 16 + erow;
            int cl = wn * 64 + nt * 8 + ecol;
            int r0 = rowbase + rl;
            int c0 = colbase + cl;
            float2 v0 = make_float2(acc[mt][nt][0], acc[mt][nt][1]);
            float2 v1 = make_float2(acc[mt][nt][2], acc[mt][nt][3]);
            if (EPI) {
                float2 x0 = *(const float2*)&X[(size_t)r0 * DM + c0];
                float2 x1 = *(const float2*)&X[(size_t)(r0 + 8) * DM + c0];
                float2 dv = *(const float2*)&Dv[c0];
                v0.x = fmaf(x0.x, dv.x, v0.x); v0.y = fmaf(x0.y, dv.y, v0.y);
                v1.x = fmaf(x1.x, dv.x, v1.x); v1.y = fmaf(x1.y, dv.y, v1.y);
            }
            if (HALF_OUT) {
                __half2 q0 = __floats2half2_rn(v0.x, v0.y);
                __half2 q1 = __floats2half2_rn(v1.x, v1.y);
                __half* C = (__half*)Cm;
                *(__half2*)&C[(size_t)r0 * NGLOB + c0]       = q0;
                *(__half2*)&C[(size_t)(r0 + 8) * NGLOB + c0] = q1;
                if (FUSE_SCAN) {
                    *(uint32_t*)(smem + rl * SP_H + cl * 2)       = *(uint32_t*)&q0;
                    *(uint32_t*)(smem + (rl + 8) * SP_H + cl * 2) = *(uint32_t*)&q1;
                }
            } else {
                float* C = (float*)Cm;
                *(float2*)&C[(size_t)r0 * NGLOB + c0]       = v0;
                *(float2*)&C[(size_t)(r0 + 8) * NGLOB + c0] = v1;
            }
        }
    }

    if (FUSE_SCAN) {
        __syncthreads();
        int ch = tid & 63;
        int ck = tid >> 6;
        float2 lam = g_lam[(colbase >> 1) + ch];
        float hr = 0.f, hi = 0.f;
        const char* sp = smem + ck * 32 * SP_H + ch * 4;
        #pragma unroll 8
        for (int t = 0; t < CHUNK; t++) {
            uint32_t u = *(const uint32_t*)(sp + t * SP_H);
            __half2 hv = *(__half2*)&u;
            float br = __low2float(hv), bi = __high2float(hv);
            float nr = fmaf(lam.x, hr, fmaf(-lam.y, hi, br));
            float ni = fmaf(lam.x, hi, fmaf( lam.y, hr, bi));
            hr = nr; hi = ni;
        }
        int chunk = blockIdx.y * 4 + ck;
        *(float2*)&g_carryf[(size_t)chunk * NW1 + colbase + 2 * ch] =
            make_float2(hr, hi);
    }
}

// Wrappers: bind __device__ globals from DEVICE code only.
__global__ void __launch_bounds__(256, 2) gemm1_k() {
    mm_gemm_body<DM, NW1, false, true, true>(g_xf, g_W1f, g_BuH, nullptr, nullptr);
}
__global__ void __launch_bounds__(256, 2) gemm2_k(float* __restrict__ y,
                                                  const float* __restrict__ X,
                                                  const float* __restrict__ Dv) {
    mm_gemm_body<NW1, DM, true, false, false>(g_hf, g_W2f, y, X, Dv);
}

// ---------------- chunk prefix: serial-4 / warp-KS / cross-warp hybrid -------
// Grid 128 (j = channel pair), 256 threads. Thread t covers chunks [4t, 4t+4).
// 2 __syncthreads total (vs 20 in block-KS).
__global__ void __launch_bounds__(256) chunk_prefix_hyb() {
    __shared__ float4 s_tot[8], s_ex[8];
    const int j = blockIdx.x;
    const int tid = threadIdx.x, w = tid >> 5, lane = tid & 31;
    const float2 lt0 = g_lamPow[2 * j];          // lambda^32, channel 2j
    const float2 lt1 = g_lamPow[2 * j + 1];      //            channel 2j+1
    const float4* carry = (const float4*)g_carryf;
    float4* hinit = (float4*)g_hinitf;
    const int ct0 = tid * 4;

    // pass A: serial inclusive over my 4 chunks (carries kept in regs)
    float4 cr[4];
    float4 b = make_float4(0.f, 0.f, 0.f, 0.f);
    #pragma unroll
    for (int i = 0; i < 4; i++) {
        cr[i] = carry[(size_t)(ct0 + i) * 128 + j];
        b = cstep(lt0, lt1, b, cr[i]);
    }
    // warp KS over threads (segment = 4 chunks; multiplier λ^(128·2^s))
    #pragma unroll
    for (int s = 0; s < 5; s++) {
        int d = 1 << s;
        float4 up = shfl_up4(b, d);
        float2 p0 = g_lamPow[(2 + s) * DH + 2 * j];
        float2 p1 = g_lamPow[(2 + s) * DH + 2 * j + 1];
        if (lane >= d) {
            b.x += p0.x * up.x - p0.y * up.y;
            b.y += p0.x * up.y + p0.y * up.x;
            b.z += p1.x * up.z - p1.y * up.w;
            b.w += p1.x * up.w + p1.y * up.z;
        }
    }
    if (lane == 31) s_tot[w] = b;
    __syncthreads();
    if (tid == 0) {    // serial exclusive over 8 warp totals (λ^4096 per warp)
        float2 q0 = g_lamPow[7 * DH + 2 * j];
        float2 q1 = g_lamPow[7 * DH + 2 * j + 1];
        float4 e = make_float4(0.f, 0.f, 0.f, 0.f);
        #pragma unroll
        for (int ww = 0; ww < 8; ww++) {
            s_ex[ww] = e;
            e = cstep(q0, q1, e, s_tot[ww]);
        }
    }
    __syncthreads();
    // thread exclusive: ex = λ^(128·lane) · ex_warp + prev_inclusive
    float4 exw = s_ex[w];
    float4 prev = shfl_up4(b, 1);
    if (lane == 0) prev = make_float4(0.f, 0.f, 0.f, 0.f);
    float2 a0 = make_float2(1.f, 0.f), a1 = make_float2(1.f, 0.f);
    #pragma unroll
    for (int k = 0; k < 5; k++) {
        if ((lane >> k) & 1) {
            float2 p0 = g_lamPow[(2 + k) * DH + 2 * j];
            float2 p1 = g_lamPow[(2 + k) * DH + 2 * j + 1];
            float2 n0 = make_float2(a0.x * p0.x - a0.y * p0.y, a0.x * p0.y + a0.y * p0.x);
            float2 n1 = make_float2(a1.x * p1.x - a1.y * p1.y, a1.x * p1.y + a1.y * p1.x);
            a0 = n0; a1 = n1;
        }
    }
    float4 e;
    e.x = prev.x + a0.x * exw.x - a0.y * exw.y;
    e.y = prev.y + a0.x * exw.y + a0.y * exw.x;
    e.z = prev.z + a1.x * exw.z - a1.y * exw.w;
    e.w = prev.w + a1.x * exw.w + a1.y * exw.z;
    // pass B: emit hinit for my 4 chunks
    #pragma unroll
    for (int i = 0; i < 4; i++) {
        hinit[(size_t)(ct0 + i) * 128 + j] = e;
        e = cstep(lt0, lt1, e, cr[i]);
    }
}

// ---------------- scan_apply: fp16 Bu -> fp16 h ------------------------------
__global__ void scan_apply() {
    int c = blockIdx.x, j = threadIdx.x;   // j: 0..127, 2 complex channels each
    float2 l0 = g_lam[2 * j], l1 = g_lam[2 * j + 1];
    float4 h = ((const float4*)g_hinitf)[(size_t)c * 128 + j];
    const uint2* base = (const uint2*)(g_BuH + (size_t)c * CHUNK * NW1) + j;
    __half* of = g_hf + (size_t)c * CHUNK * NW1 + 4 * j;
    #pragma unroll 8
    for (int t = 0; t < CHUNK; t++) {
        uint2 u = base[(size_t)t * 128];
        __half2 b0 = *(__half2*)&u.x;
        __half2 b1 = *(__half2*)&u.y;
        float nr0 = fmaf(l0.x, h.x, fmaf(-l0.y, h.y, __low2float(b0)));
        float ni0 = fmaf(l0.x, h.y, fmaf( l0.y, h.x, __high2float(b0)));
        float nr1 = fmaf(l1.x, h.z, fmaf(-l1.y, h.w, __low2float(b1)));
        float ni1 = fmaf(l1.x, h.w, fmaf( l1.y, h.z, __high2float(b1)));
        h = make_float4(nr0, ni0, nr1, ni1);
        __half2 p0 = __floats2half2_rn(nr0, ni0);
        __half2 p1 = __floats2half2_rn(nr1, ni1);
        uint2 o;
        o.x = *reinterpret_cast<uint32_t*>(&p0);
        o.y = *reinterpret_cast<uint32_t*>(&p1);
        *reinterpret_cast<uint2*>(of + (size_t)t * NW1) = o;
    }
}

// ---------------- entry ----------------
extern "C" void kernel_launch(void* const* d_in, const int* in_sizes, int n_in,
                              void* d_out, int out_size) {
    const float* x         = (const float*)d_in[0];
    const float* nu_log    = (const float*)d_in[1];
    const float* theta_log = (const float*)d_in[2];
    const float* gamma_log = (const float*)d_in[3];
    const float* B_re      = (const float*)d_in[4];
    const float* B_im      = (const float*)d_in[5];
    const float* C_re      = (const float*)d_in[6];
    const float* C_im      = (const float*)d_in[7];
    const float* Dv        = (const float*)d_in[8];
    float* y = (float*)d_out;

    cudaFuncSetAttribute(gemm1_k, cudaFuncAttributeMaxDynamicSharedMemorySize, SMEM_G);
    cudaFuncSetAttribute(gemm2_k, cudaFuncAttributeMaxDynamicSharedMemorySize, SMEM_G);

    // weights + params + x-convert in one launch
    setup_all<<<512 + (L_SEQ * DM / 4) / 256, 256>>>(
        nu_log, theta_log, gamma_log, B_re, B_im, C_re, C_im, x);

    // GEMM1 (+ fused per-chunk carry scan): BuH = x @ W1T^T
    gemm1_k<<<dim3(NW1 / 128, L_SEQ / 128), 256, SMEM_G>>>();

    chunk_prefix_hyb<<<128, 256>>>();
    scan_apply<<<NCHUNK, 128>>>();

    // GEMM2: y = h @ W2T^T + x*D
    gemm2_k<<<dim3(DM / 128, L_SEQ / 128), 256, SMEM_G>>>(y, x, Dv);
}

// round 14
// speedup vs baseline: 1.2516x; 1.0156x over previous
#include <cuda_runtime.h>
#include <cuda_fp16.h>
#include <cmath>
#include <cstdint>

#define L_SEQ  32768
#define DM     256
#define DH     256
#define NW1    512
#define CHUNK  16
#define NCHUNK (L_SEQ / CHUNK)   // 2048
#define NPOW   10                // lamPow[s] = lambda^(CHUNK * 2^s), s=0..9

// ---------------- scratch ----------------
// Channel-interleaved layout: col 2h = re_h, col 2h+1 = im_h.
__device__ __half  g_BuH[(size_t)L_SEQ * NW1];    // GEMM1 out (fp16), scan input
__device__ __half  g_xf[(size_t)L_SEQ * DM];      // x in fp16
__device__ __half  g_hf[(size_t)L_SEQ * NW1];     // h in fp16 (scan output)
__device__ __half  g_W1f[NW1 * DM];               // [512][256]
__device__ __half  g_W2f[DM * NW1];               // [256][512]
__device__ float2  g_lam[DH];
__device__ float2  g_lamPow[NPOW * DH];
__device__ float   g_carryf[(size_t)NCHUNK * NW1];
__device__ float   g_hinitf[(size_t)NCHUNK * NW1];

// ---------------- PTX helpers ----------------
__device__ __forceinline__ uint32_t smem_u32(const void* p) {
    uint32_t a;
    asm("{ .reg .u64 t; cvta.to.shared.u64 t, %1; cvt.u32.u64 %0, t; }" : "=r"(a) : "l"(p));
    return a;
}
__device__ __forceinline__ void cp16(uint32_t s, const void* g) {
    asm volatile("cp.async.cg.shared.global [%0], [%1], 16;" :: "r"(s), "l"(g));
}
__device__ __forceinline__ void cp_commit() {
    asm volatile("cp.async.commit_group;" ::: "memory");
}
__device__ __forceinline__ void ldsm4(uint32_t addr, uint32_t* r) {
    asm volatile("ldmatrix.sync.aligned.m8n8.x4.shared.b16 {%0,%1,%2,%3}, [%4];"
                 : "=r"(r[0]), "=r"(r[1]), "=r"(r[2]), "=r"(r[3]) : "r"(addr));
}
__device__ __forceinline__ void mma_f16(float* c, const uint32_t* a, const uint32_t* b) {
    asm volatile("mma.sync.aligned.m16n8k16.row.col.f32.f16.f16.f32 "
                 "{%0,%1,%2,%3},{%4,%5,%6,%7},{%8,%9},{%0,%1,%2,%3};"
                 : "+f"(c[0]), "+f"(c[1]), "+f"(c[2]), "+f"(c[3])
                 : "r"(a[0]), "r"(a[1]), "r"(a[2]), "r"(a[3]), "r"(b[0]), "r"(b[1]));
}

// step both channels: out = lam * h + v   (complex per float2 half)
__device__ __forceinline__ float4 cstep(float2 l0, float2 l1, float4 h, float4 v) {
    float4 o;
    o.x = fmaf(l0.x, h.x, fmaf(-l0.y, h.y, v.x));
    o.y = fmaf(l0.x, h.y, fmaf( l0.y, h.x, v.y));
    o.z = fmaf(l1.x, h.z, fmaf(-l1.y, h.w, v.z));
    o.w = fmaf(l1.x, h.w, fmaf( l1.y, h.z, v.w));
    return o;
}
__device__ __forceinline__ float4 shfl_up4(float4 v, int d) {
    float4 o;
    o.x = __shfl_up_sync(0xffffffffu, v.x, d);
    o.y = __shfl_up_sync(0xffffffffu, v.y, d);
    o.z = __shfl_up_sync(0xffffffffu, v.z, d);
    o.w = __shfl_up_sync(0xffffffffu, v.w, d);
    return o;
}

// ---------------- setup (params + weights + x convert, one kernel) -----------
__global__ void setup_all(const float* __restrict__ nu_log,
                          const float* __restrict__ theta_log,
                          const float* __restrict__ gamma_log,
                          const float* __restrict__ B_re,
                          const float* __restrict__ B_im,
                          const float* __restrict__ C_re,
                          const float* __restrict__ C_im,
                          const float* __restrict__ x) {
    int blk = blockIdx.x;
    int t = threadIdx.x;  // 0..255
    if (blk < 512) {      // weights
        int n = blk;      // channel-interleaved (2h=re, 2h+1=im)
        int h = n >> 1;
        int im = n & 1;
        float g = expf(gamma_log[h]);
        float w = (im ? B_im[h * DM + t] : B_re[h * DM + t]) * g;
        g_W1f[n * DM + t] = __float2half(w);
        float c2 = im ? -C_im[t * DH + h] : C_re[t * DH + h];
        g_W2f[t * NW1 + n] = __float2half(c2);
        if (n == 0) {     // block 0: lambda params (t = channel)
            double nu = exp((double)nu_log[t]);
            double th = exp((double)theta_log[t]);
            double r  = exp(-nu);
            g_lam[t]  = make_float2((float)(r * cos(th)), (float)(r * sin(th)));
            #pragma unroll
            for (int s = 0; s < NPOW; s++) {
                double sc = (double)CHUNK * (double)(1 << s);
                double rr = exp(-sc * nu);
                double aa = sc * th;
                g_lamPow[s * DH + t] =
                    make_float2((float)(rr * cos(aa)), (float)(rr * sin(aa)));
            }
        }
    } else {              // x -> fp16
        size_t i = (size_t)(blk - 512) * 256 + t;   // float4 index
        float4 v = ((const float4*)x)[i];
        __half2 p0 = __floats2half2_rn(v.x, v.y);
        __half2 p1 = __floats2half2_rn(v.z, v.w);
        uint2 u;
        u.x = *reinterpret_cast<uint32_t*>(&p0);
        u.y = *reinterpret_cast<uint32_t*>(&p1);
        *reinterpret_cast<uint2*>(g_xf + i * 4) = u;
    }
}

// ---------------- fp16 mma.sync GEMM (KC=32, 4-stage, 1 sync/chunk) ----------
#define KC      32
#define PITCH   80
#define TILE_B  (128 * PITCH)              // 10240
#define NSTAGE  4
#define STAGE_B (2 * TILE_B)               // 20480
#define SMEM_G  (NSTAGE * STAGE_B)         // 81920 per CTA (x2 CTA/SM)
#define O_A 0
#define O_B TILE_B
#define SP_H 272                           // fp16 stash pitch (4-bank row shift)

template<int KTOT, int NGLOB, bool EPI, bool FUSE_SCAN, bool HALF_OUT>
__device__ __forceinline__ void mm_gemm_body(
    const __half* __restrict__ A, const __half* __restrict__ B,
    void* __restrict__ Cm, const float* __restrict__ X, const float* __restrict__ Dv)
{
    extern __shared__ char smem[];
    const uint32_t sb = smem_u32(smem);
    const int tid = threadIdx.x, wid = tid >> 5, l = tid & 31;
    const int rowbase = blockIdx.y * 128;
    const int colbase = blockIdx.x * 128;
    const int wm = wid & 3, wn = wid >> 2;

    float acc[2][8][4];
    #pragma unroll
    for (int i = 0; i < 2; i++)
        #pragma unroll
        for (int j = 0; j < 8; j++)
            #pragma unroll
            for (int q = 0; q < 4; q++) acc[i][j][q] = 0.f;

    const int srow = tid >> 1;
    const int sq   = (tid & 1) * 2;

    auto load_stage = [&](int c) {
        const uint32_t base = sb + (c & (NSTAGE - 1)) * STAGE_B;
        const int k0 = c * KC;
        const __half* gA = A + (size_t)(rowbase + srow) * KTOT + k0;
        const __half* gB = B + (size_t)(colbase + srow) * KTOT + k0;
        #pragma unroll
        for (int d = 0; d < 2; d++) {
            int q = sq + d;
            uint32_t so = srow * PITCH + q * 16;
            cp16(base + O_A + so, gA + q * 8);
            cp16(base + O_B + so, gB + q * 8);
        }
    };

    auto compute = [&](int c) {
        const uint32_t base = sb + (c & (NSTAGE - 1)) * STAGE_B;
        #pragma unroll
        for (int kk = 0; kk < 2; kk++) {
            const int k16 = kk * 16;
            uint32_t av[2][4], bv[4][4];
            const uint32_t arow_off =
                (uint32_t)(wm * 32 + (l & 15)) * PITCH + (uint32_t)(k16 + ((l >> 4) << 3)) * 2;
            const int g = l >> 3;
            const int nadd = ((g & 2) << 2) + (l & 7);
            const int kadd = k16 + ((g & 1) << 3);
            #pragma unroll
            for (int mt = 0; mt < 2; mt++)
                ldsm4(base + O_A + arow_off + (uint32_t)(mt * 16) * PITCH, av[mt]);
            #pragma unroll
            for (int p = 0; p < 4; p++)
                ldsm4(base + O_B + (uint32_t)(wn * 64 + p * 16 + nadd) * PITCH
                           + (uint32_t)kadd * 2, bv[p]);
            #pragma unroll
            for (int mt = 0; mt < 2; mt++)
                #pragma unroll
                for (int nt = 0; nt < 8; nt++)
                    mma_f16(acc[mt][nt], av[mt], &bv[nt >> 1][(nt & 1) * 2]);
        }
    };

    // Single __syncthreads per chunk (safety argument: see round-12 comment).
    const int NCH = KTOT / KC;
    #pragma unroll
    for (int s = 0; s < NSTAGE - 1; s++) { load_stage(s); cp_commit(); }
    for (int c = 0; c < NCH; c++) {
        asm volatile("cp.async.wait_group %0;" :: "n"(NSTAGE - 2) : "memory");
        __syncthreads();
        compute(c);
        if (c + NSTAGE - 1 < NCH) load_stage(c + NSTAGE - 1);
        cp_commit();
    }

    const int erow = (l >> 2);
    const int ecol = (l & 3) * 2;
    #pragma unroll
    for (int mt = 0; mt < 2; mt++) {
        #pragma unroll
        for (int nt = 0; nt < 8; nt++) {
            int rl = wm * 32 + mt * 16 + erow;
            int cl = wn * 64 + nt * 8 + ecol;
            int r0 = rowbase + rl;
            int c0 = colbase + cl;
            float2 v0 = make_float2(acc[mt][nt][0], acc[mt][nt][1]);
            float2 v1 = make_float2(acc[mt][nt][2], acc[mt][nt][3]);
            if (EPI) {
                float2 x0 = *(const float2*)&X[(size_t)r0 * DM + c0];
                float2 x1 = *(const float2*)&X[(size_t)(r0 + 8) * DM + c0];
                float2 dv = *(const float2*)&Dv[c0];
                v0.x = fmaf(x0.x, dv.x, v0.x); v0.y = fmaf(x0.y, dv.y, v0.y);
                v1.x = fmaf(x1.x, dv.x, v1.x); v1.y = fmaf(x1.y, dv.y, v1.y);
            }
            if (HALF_OUT) {
                __half2 q0 = __floats2half2_rn(v0.x, v0.y);
                __half2 q1 = __floats2half2_rn(v1.x, v1.y);
                __half* C = (__half*)Cm;
                *(__half2*)&C[(size_t)r0 * NGLOB + c0]       = q0;
                *(__half2*)&C[(size_t)(r0 + 8) * NGLOB + c0] = q1;
                if (FUSE_SCAN) {
                    *(uint32_t*)(smem + rl * SP_H + cl * 2)       = *(uint32_t*)&q0;
                    *(uint32_t*)(smem + (rl + 8) * SP_H + cl * 2) = *(uint32_t*)&q1;
                }
            } else {
                float* C = (float*)Cm;
                *(float2*)&C[(size_t)r0 * NGLOB + c0]       = v0;
                *(float2*)&C[(size_t)(r0 + 8) * NGLOB + c0] = v1;
            }
        }
    }

    if (FUSE_SCAN) {
        __syncthreads();
        // 8 sub-chunks of 16 rows x 64 channels = 512 scans; 256 threads x 2
        int ch = tid & 63;
        float2 lam = g_lam[(colbase >> 1) + ch];
        #pragma unroll
        for (int r = 0; r < 2; r++) {
            int ck = (tid >> 6) + r * 4;     // sub-chunk 0..7
            float hr = 0.f, hi = 0.f;
            const char* sp = smem + ck * CHUNK * SP_H + ch * 4;
            #pragma unroll 8
            for (int t = 0; t < CHUNK; t++) {
                uint32_t u = *(const uint32_t*)(sp + t * SP_H);
                __half2 hv = *(__half2*)&u;
                float br = __low2float(hv), bi = __high2float(hv);
                float nr = fmaf(lam.x, hr, fmaf(-lam.y, hi, br));
                float ni = fmaf(lam.x, hi, fmaf( lam.y, hr, bi));
                hr = nr; hi = ni;
            }
            int chunk = blockIdx.y * 8 + ck;
            *(float2*)&g_carryf[(size_t)chunk * NW1 + colbase + 2 * ch] =
                make_float2(hr, hi);
        }
    }
}

// Wrappers: bind __device__ globals from DEVICE code only.
__global__ void __launch_bounds__(256, 2) gemm1_k() {
    mm_gemm_body<DM, NW1, false, true, true>(g_xf, g_W1f, g_BuH, nullptr, nullptr);
}
__global__ void __launch_bounds__(256, 2) gemm2_k(float* __restrict__ y,
                                                  const float* __restrict__ X,
                                                  const float* __restrict__ Dv) {
    mm_gemm_body<NW1, DM, true, false, false>(g_hf, g_W2f, y, X, Dv);
}

// ---------------- chunk prefix: serial-8 / warp-KS / cross-warp hybrid -------
// Grid 128 (j = channel pair), 256 threads. Thread t covers chunks [8t, 8t+8).
// Multipliers: serial lamPow[0] (λ^16); warp-KS segment = 8 chunks = 128 steps
// -> lamPow[3+s]; warp total = 4096 steps -> lamPow[8].
__global__ void __launch_bounds__(256) chunk_prefix_hyb() {
    __shared__ float4 s_tot[8], s_ex[8];
    const int j = blockIdx.x;
    const int tid = threadIdx.x, w = tid >> 5, lane = tid & 31;
    const float2 lt0 = g_lamPow[2 * j];
    const float2 lt1 = g_lamPow[2 * j + 1];
    const float4* carry = (const float4*)g_carryf;
    float4* hinit = (float4*)g_hinitf;
    const int ct0 = tid * 8;

    // pass A: serial inclusive over my 8 chunks (carries kept in regs)
    float4 cr[8];
    float4 b = make_float4(0.f, 0.f, 0.f, 0.f);
    #pragma unroll
    for (int i = 0; i < 8; i++) {
        cr[i] = carry[(size_t)(ct0 + i) * 128 + j];
        b = cstep(lt0, lt1, b, cr[i]);
    }
    // warp KS over threads (segment = 8 chunks; multiplier λ^(128·2^s))
    #pragma unroll
    for (int s = 0; s < 5; s++) {
        int d = 1 << s;
        float4 up = shfl_up4(b, d);
        float2 p0 = g_lamPow[(3 + s) * DH + 2 * j];
        float2 p1 = g_lamPow[(3 + s) * DH + 2 * j + 1];
        if (lane >= d) {
            b.x += p0.x * up.x - p0.y * up.y;
            b.y += p0.x * up.y + p0.y * up.x;
            b.z += p1.x * up.z - p1.y * up.w;
            b.w += p1.x * up.w + p1.y * up.z;
        }
    }
    if (lane == 31) s_tot[w] = b;
    __syncthreads();
    if (tid == 0) {    // serial exclusive over 8 warp totals (λ^4096 per warp)
        float2 q0 = g_lamPow[8 * DH + 2 * j];
        float2 q1 = g_lamPow[8 * DH + 2 * j + 1];
        float4 e = make_float4(0.f, 0.f, 0.f, 0.f);
        #pragma unroll
        for (int ww = 0; ww < 8; ww++) {
            s_ex[ww] = e;
            e = cstep(q0, q1, e, s_tot[ww]);
        }
    }
    __syncthreads();
    // thread exclusive: ex = λ^(128·lane) · ex_warp + prev_inclusive
    float4 exw = s_ex[w];
    float4 prev = shfl_up4(b, 1);
    if (lane == 0) prev = make_float4(0.f, 0.f, 0.f, 0.f);
    float2 a0 = make_float2(1.f, 0.f), a1 = make_float2(1.f, 0.f);
    #pragma unroll
    for (int k = 0; k < 5; k++) {
        if ((lane >> k) & 1) {
            float2 p0 = g_lamPow[(3 + k) * DH + 2 * j];
            float2 p1 = g_lamPow[(3 + k) * DH + 2 * j + 1];
            float2 n0 = make_float2(a0.x * p0.x - a0.y * p0.y, a0.x * p0.y + a0.y * p0.x);
            float2 n1 = make_float2(a1.x * p1.x - a1.y * p1.y, a1.x * p1.y + a1.y * p1.x);
            a0 = n0; a1 = n1;
        }
    }
    float4 e;
    e.x = prev.x + a0.x * exw.x - a0.y * exw.y;
    e.y = prev.y + a0.x * exw.y + a0.y * exw.x;
    e.z = prev.z + a1.x * exw.z - a1.y * exw.w;
    e.w = prev.w + a1.x * exw.w + a1.y * exw.z;
    // pass B: emit hinit for my 8 chunks
    #pragma unroll
    for (int i = 0; i < 8; i++) {
        hinit[(size_t)(ct0 + i) * 128 + j] = e;
        e = cstep(lt0, lt1, e, cr[i]);
    }
}

// ---------------- scan_apply: fp16 Bu -> fp16 h ------------------------------
__global__ void scan_apply() {
    int c = blockIdx.x, j = threadIdx.x;   // j: 0..127, 2 complex channels each
    float2 l0 = g_lam[2 * j], l1 = g_lam[2 * j + 1];
    float4 h = ((const float4*)g_hinitf)[(size_t)c * 128 + j];
    const uint2* base = (const uint2*)(g_BuH + (size_t)c * CHUNK * NW1) + j;
    __half* of = g_hf + (size_t)c * CHUNK * NW1 + 4 * j;
    #pragma unroll
    for (int t = 0; t < CHUNK; t++) {
        uint2 u = base[(size_t)t * 128];
        __half2 b0 = *(__half2*)&u.x;
        __half2 b1 = *(__half2*)&u.y;
        float nr0 = fmaf(l0.x, h.x, fmaf(-l0.y, h.y, __low2float(b0)));
        float ni0 = fmaf(l0.x, h.y, fmaf( l0.y, h.x, __high2float(b0)));
        float nr1 = fmaf(l1.x, h.z, fmaf(-l1.y, h.w, __low2float(b1)));
        float ni1 = fmaf(l1.x, h.w, fmaf( l1.y, h.z, __high2float(b1)));
        h = make_float4(nr0, ni0, nr1, ni1);
        __half2 p0 = __floats2half2_rn(nr0, ni0);
        __half2 p1 = __floats2half2_rn(nr1, ni1);
        uint2 o;
        o.x = *reinterpret_cast<uint32_t*>(&p0);
        o.y = *reinterpret_cast<uint32_t*>(&p1);
        *reinterpret_cast<uint2*>(of + (size_t)t * NW1) = o;
    }
}

// ---------------- entry ----------------
extern "C" void kernel_launch(void* const* d_in, const int* in_sizes, int n_in,
                              void* d_out, int out_size) {
    const float* x         = (const float*)d_in[0];
    const float* nu_log    = (const float*)d_in[1];
    const float* theta_log = (const float*)d_in[2];
    const float* gamma_log = (const float*)d_in[3];
    const float* B_re      = (const float*)d_in[4];
    const float* B_im      = (const float*)d_in[5];
    const float* C_re      = (const float*)d_in[6];
    const float* C_im      = (const float*)d_in[7];
    const float* Dv        = (const float*)d_in[8];
    float* y = (float*)d_out;

    cudaFuncSetAttribute(gemm1_k, cudaFuncAttributeMaxDynamicSharedMemorySize, SMEM_G);
    cudaFuncSetAttribute(gemm2_k, cudaFuncAttributeMaxDynamicSharedMemorySize, SMEM_G);

    // weights + params + x-convert in one launch
    setup_all<<<512 + (L_SEQ * DM / 4) / 256, 256>>>(
        nu_log, theta_log, gamma_log, B_re, B_im, C_re, C_im, x);

    // GEMM1 (+ fused per-chunk carry scan): BuH = x @ W1T^T
    gemm1_k<<<dim3(NW1 / 128, L_SEQ / 128), 256, SMEM_G>>>();

    chunk_prefix_hyb<<<128, 256>>>();
    scan_apply<<<NCHUNK, 128>>>();

    // GEMM2: y = h @ W2T^T + x*D
    gemm2_k<<<dim3(DM / 128, L_SEQ / 128), 256, SMEM_G>>>(y, x, Dv);
}

// round 15
// speedup vs baseline: 1.2603x; 1.0070x over previous
#include <cuda_runtime.h>
#include <cuda_fp16.h>
#include <cmath>
#include <cstdint>

#define L_SEQ  32768
#define DM     256
#define DH     256
#define NW1    512
#define CHUNK  16
#define NCHUNK (L_SEQ / CHUNK)   // 2048
#define NPOW   10                // lamPow[s] = lambda^(CHUNK * 2^s), s=0..9

// ---------------- scratch ----------------
// Channel-interleaved layout: col 2h = re_h, col 2h+1 = im_h.
__device__ __half  g_BuH[(size_t)L_SEQ * NW1];    // GEMM1 out (fp16): Bu
__device__ __half  g_xf[(size_t)L_SEQ * DM];      // x in fp16
__device__ __half  g_W1f[NW1 * DM];               // [512][256]
__device__ __half  g_W2f[DM * NW1];               // [256][512]
__device__ float2  g_lam[DH];
__device__ float2  g_lamPow[NPOW * DH];
__device__ float   g_carryf[(size_t)NCHUNK * NW1];
__device__ float   g_hinitf[(size_t)NCHUNK * NW1];

// ---------------- PTX helpers ----------------
__device__ __forceinline__ uint32_t smem_u32(const void* p) {
    uint32_t a;
    asm("{ .reg .u64 t; cvta.to.shared.u64 t, %1; cvt.u32.u64 %0, t; }" : "=r"(a) : "l"(p));
    return a;
}
__device__ __forceinline__ void cp16(uint32_t s, const void* g) {
    asm volatile("cp.async.cg.shared.global [%0], [%1], 16;" :: "r"(s), "l"(g));
}
__device__ __forceinline__ void cp_commit() {
    asm volatile("cp.async.commit_group;" ::: "memory");
}
__device__ __forceinline__ void ldsm4(uint32_t addr, uint32_t* r) {
    asm volatile("ldmatrix.sync.aligned.m8n8.x4.shared.b16 {%0,%1,%2,%3}, [%4];"
                 : "=r"(r[0]), "=r"(r[1]), "=r"(r[2]), "=r"(r[3]) : "r"(addr));
}
__device__ __forceinline__ void mma_f16(float* c, const uint32_t* a, const uint32_t* b) {
    asm volatile("mma.sync.aligned.m16n8k16.row.col.f32.f16.f16.f32 "
                 "{%0,%1,%2,%3},{%4,%5,%6,%7},{%8,%9},{%0,%1,%2,%3};"
                 : "+f"(c[0]), "+f"(c[1]), "+f"(c[2]), "+f"(c[3])
                 : "r"(a[0]), "r"(a[1]), "r"(a[2]), "r"(a[3]), "r"(b[0]), "r"(b[1]));
}

// step both channels: out = lam * h + v   (complex per float2 half)
__device__ __forceinline__ float4 cstep(float2 l0, float2 l1, float4 h, float4 v) {
    float4 o;
    o.x = fmaf(l0.x, h.x, fmaf(-l0.y, h.y, v.x));
    o.y = fmaf(l0.x, h.y, fmaf( l0.y, h.x, v.y));
    o.z = fmaf(l1.x, h.z, fmaf(-l1.y, h.w, v.z));
    o.w = fmaf(l1.x, h.w, fmaf( l1.y, h.z, v.w));
    return o;
}
__device__ __forceinline__ float4 shfl_up4(float4 v, int d) {
    float4 o;
    o.x = __shfl_up_sync(0xffffffffu, v.x, d);
    o.y = __shfl_up_sync(0xffffffffu, v.y, d);
    o.z = __shfl_up_sync(0xffffffffu, v.z, d);
    o.w = __shfl_up_sync(0xffffffffu, v.w, d);
    return o;
}

// ---------------- setup (params + weights + x convert, one kernel) -----------
__global__ void setup_all(const float* __restrict__ nu_log,
                          const float* __restrict__ theta_log,
                          const float* __restrict__ gamma_log,
                          const float* __restrict__ B_re,
                          const float* __restrict__ B_im,
                          const float* __restrict__ C_re,
                          const float* __restrict__ C_im,
                          const float* __restrict__ x) {
    int blk = blockIdx.x;
    int t = threadIdx.x;  // 0..255
    if (blk < 512) {      // weights
        int n = blk;      // channel-interleaved (2h=re, 2h+1=im)
        int h = n >> 1;
        int im = n & 1;
        float g = expf(gamma_log[h]);
        float w = (im ? B_im[h * DM + t] : B_re[h * DM + t]) * g;
        g_W1f[n * DM + t] = __float2half(w);
        float c2 = im ? -C_im[t * DH + h] : C_re[t * DH + h];
        g_W2f[t * NW1 + n] = __float2half(c2);
        if (n == 0) {     // block 0: lambda params (t = channel)
            double nu = exp((double)nu_log[t]);
            double th = exp((double)theta_log[t]);
            double r  = exp(-nu);
            g_lam[t]  = make_float2((float)(r * cos(th)), (float)(r * sin(th)));
            #pragma unroll
            for (int s = 0; s < NPOW; s++) {
                double sc = (double)CHUNK * (double)(1 << s);
                double rr = exp(-sc * nu);
                double aa = sc * th;
                g_lamPow[s * DH + t] =
                    make_float2((float)(rr * cos(aa)), (float)(rr * sin(aa)));
            }
        }
    } else {              // x -> fp16
        size_t i = (size_t)(blk - 512) * 256 + t;   // float4 index
        float4 v = ((const float4*)x)[i];
        __half2 p0 = __floats2half2_rn(v.x, v.y);
        __half2 p1 = __floats2half2_rn(v.z, v.w);
        uint2 u;
        u.x = *reinterpret_cast<uint32_t*>(&p0);
        u.y = *reinterpret_cast<uint32_t*>(&p1);
        *reinterpret_cast<uint2*>(g_xf + i * 4) = u;
    }
}

// ---------------- fp16 mma.sync GEMM (KC=32, 4-stage, 1 sync/chunk) ----------
#define KC      32
#define PITCH   80
#define TILE_B  (128 * PITCH)              // 10240
#define NSTAGE  4
#define STAGE_B (2 * TILE_B)               // 20480
#define SMEM_G  (NSTAGE * STAGE_B)         // 81920 per CTA (x2 CTA/SM)
#define O_A 0
#define O_B TILE_B
#define SP_H 272                           // fp16 stash pitch (4-bank row shift)

// FUSE_SCAN  (gemm1): epilogue stash + per-chunk carry scans.
// FUSE_APPLY (gemm2): A tile holds Bu; scan it into h in-place before MMAs,
//                     seeded by g_hinitf per 16-row sub-chunk. Arithmetic is
//                     identical to the old scan_apply kernel.
template<int KTOT, int NGLOB, bool EPI, bool FUSE_SCAN, bool FUSE_APPLY, bool HALF_OUT>
__device__ __forceinline__ void mm_gemm_body(
    const __half* __restrict__ A, const __half* __restrict__ B,
    void* __restrict__ Cm, const float* __restrict__ X, const float* __restrict__ Dv)
{
    extern __shared__ char smem[];
    const uint32_t sb = smem_u32(smem);
    const int tid = threadIdx.x, wid = tid >> 5, l = tid & 31;
    const int rowbase = blockIdx.y * 128;
    const int colbase = blockIdx.x * 128;
    const int wm = wid & 3, wn = wid >> 2;

    float acc[2][8][4];
    #pragma unroll
    for (int i = 0; i < 2; i++)
        #pragma unroll
        for (int j = 0; j < 8; j++)
            #pragma unroll
            for (int q = 0; q < 4; q++) acc[i][j][q] = 0.f;

    const int srow = tid >> 1;
    const int sq   = (tid & 1) * 2;

    auto load_stage = [&](int c) {
        const uint32_t base = sb + (c & (NSTAGE - 1)) * STAGE_B;
        const int k0 = c * KC;
        const __half* gA = A + (size_t)(rowbase + srow) * KTOT + k0;
        const __half* gB = B + (size_t)(colbase + srow) * KTOT + k0;
        #pragma unroll
        for (int d = 0; d < 2; d++) {
            int q = sq + d;
            uint32_t so = srow * PITCH + q * 16;
            cp16(base + O_A + so, gA + q * 8);
            cp16(base + O_B + so, gB + q * 8);
        }
    };

    auto compute = [&](int c) {
        const uint32_t base = sb + (c & (NSTAGE - 1)) * STAGE_B;
        #pragma unroll
        for (int kk = 0; kk < 2; kk++) {
            const int k16 = kk * 16;
            uint32_t av[2][4], bv[4][4];
            const uint32_t arow_off =
                (uint32_t)(wm * 32 + (l & 15)) * PITCH + (uint32_t)(k16 + ((l >> 4) << 3)) * 2;
            const int g = l >> 3;
            const int nadd = ((g & 2) << 2) + (l & 7);
            const int kadd = k16 + ((g & 1) << 3);
            #pragma unroll
            for (int mt = 0; mt < 2; mt++)
                ldsm4(base + O_A + arow_off + (uint32_t)(mt * 16) * PITCH, av[mt]);
            #pragma unroll
            for (int p = 0; p < 4; p++)
                ldsm4(base + O_B + (uint32_t)(wn * 64 + p * 16 + nadd) * PITCH
                           + (uint32_t)kadd * 2, bv[p]);
            #pragma unroll
            for (int mt = 0; mt < 2; mt++)
                #pragma unroll
                for (int nt = 0; nt < 8; nt++)
                    mma_f16(acc[mt][nt], av[mt], &bv[nt >> 1][(nt & 1) * 2]);
        }
    };

    // Single __syncthreads per chunk (safety argument: see round-12 comment).
    const int NCH = KTOT / KC;
    #pragma unroll
    for (int s = 0; s < NSTAGE - 1; s++) { load_stage(s); cp_commit(); }
    for (int c = 0; c < NCH; c++) {
        asm volatile("cp.async.wait_group %0;" :: "n"(NSTAGE - 2) : "memory");
        __syncthreads();
        if (FUSE_APPLY) {
            // In-place Bu -> h scan on the A tile: sub-chunk s (0..7, 16 rows)
            // x local complex channel chl (0..15). 128 independent 16-step scans.
            if (tid < 128) {
                int s   = tid >> 4;
                int chl = tid & 15;
                int gch = c * (KC / 2) + chl;           // global complex channel
                int gchunk = blockIdx.y * 8 + s;
                float2 lam = g_lam[gch];
                float2 h0 = *(const float2*)&g_hinitf[(size_t)gchunk * NW1 + 2 * gch];
                char* sp = smem + (c & (NSTAGE - 1)) * STAGE_B + O_A
                                + (s * CHUNK) * PITCH + chl * 4;
                float hr = h0.x, hi = h0.y;
                #pragma unroll
                for (int t = 0; t < CHUNK; t++) {
                    uint32_t u = *(uint32_t*)(sp + t * PITCH);
                    __half2 b2 = *(__half2*)&u;
                    float nr = fmaf(lam.x, hr, fmaf(-lam.y, hi, __low2float(b2)));
                    float ni = fmaf(lam.x, hi, fmaf( lam.y, hr, __high2float(b2)));
                    hr = nr; hi = ni;
                    __half2 o = __floats2half2_rn(nr, ni);
                    *(uint32_t*)(sp + t * PITCH) = *(uint32_t*)&o;
                }
            }
            __syncthreads();
        }
        compute(c);
        if (c + NSTAGE - 1 < NCH) load_stage(c + NSTAGE - 1);
        cp_commit();
    }

    const int erow = (l >> 2);
    const int ecol = (l & 3) * 2;
    #pragma unroll
    for (int mt = 0; mt < 2; mt++) {
        #pragma unroll
        for (int nt = 0; nt < 8; nt++) {
            int rl = wm * 32 + mt * 16 + erow;
            int cl = wn * 64 + nt * 8 + ecol;
            int r0 = rowbase + rl;
            int c0 = colbase + cl;
            float2 v0 = make_float2(acc[mt][nt][0], acc[mt][nt][1]);
            float2 v1 = make_float2(acc[mt][nt][2], acc[mt][nt][3]);
            if (EPI) {
                float2 x0 = *(const float2*)&X[(size_t)r0 * DM + c0];
                float2 x1 = *(const float2*)&X[(size_t)(r0 + 8) * DM + c0];
                float2 dv = *(const float2*)&Dv[c0];
                v0.x = fmaf(x0.x, dv.x, v0.x); v0.y = fmaf(x0.y, dv.y, v0.y);
                v1.x = fmaf(x1.x, dv.x, v1.x); v1.y = fmaf(x1.y, dv.y, v1.y);
            }
            if (HALF_OUT) {
                __half2 q0 = __floats2half2_rn(v0.x, v0.y);
                __half2 q1 = __floats2half2_rn(v1.x, v1.y);
                __half* C = (__half*)Cm;
                *(__half2*)&C[(size_t)r0 * NGLOB + c0]       = q0;
                *(__half2*)&C[(size_t)(r0 + 8) * NGLOB + c0] = q1;
                if (FUSE_SCAN) {
                    *(uint32_t*)(smem + rl * SP_H + cl * 2)       = *(uint32_t*)&q0;
                    *(uint32_t*)(smem + (rl + 8) * SP_H + cl * 2) = *(uint32_t*)&q1;
                }
            } else {
                float* C = (float*)Cm;
                *(float2*)&C[(size_t)r0 * NGLOB + c0]       = v0;
                *(float2*)&C[(size_t)(r0 + 8) * NGLOB + c0] = v1;
            }
        }
    }

    if (FUSE_SCAN) {
        __syncthreads();
        // 8 sub-chunks of 16 rows x 64 channels = 512 scans; 256 threads x 2
        int ch = tid & 63;
        float2 lam = g_lam[(colbase >> 1) + ch];
        #pragma unroll
        for (int r = 0; r < 2; r++) {
            int ck = (tid >> 6) + r * 4;     // sub-chunk 0..7
            float hr = 0.f, hi = 0.f;
            const char* sp = smem + ck * CHUNK * SP_H + ch * 4;
            #pragma unroll 8
            for (int t = 0; t < CHUNK; t++) {
                uint32_t u = *(const uint32_t*)(sp + t * SP_H);
                __half2 hv = *(__half2*)&u;
                float br = __low2float(hv), bi = __high2float(hv);
                float nr = fmaf(lam.x, hr, fmaf(-lam.y, hi, br));
                float ni = fmaf(lam.x, hi, fmaf( lam.y, hr, bi));
                hr = nr; hi = ni;
            }
            int chunk = blockIdx.y * 8 + ck;
            *(float2*)&g_carryf[(size_t)chunk * NW1 + colbase + 2 * ch] =
                make_float2(hr, hi);
        }
    }
}

// Wrappers: bind __device__ globals from DEVICE code only.
__global__ void __launch_bounds__(256, 2) gemm1_k() {
    mm_gemm_body<DM, NW1, false, true, false, true>(g_xf, g_W1f, g_BuH, nullptr, nullptr);
}
__global__ void __launch_bounds__(256, 2) gemm2_k(float* __restrict__ y,
                                                  const float* __restrict__ X,
                                                  const float* __restrict__ Dv) {
    mm_gemm_body<NW1, DM, true, false, true, false>(g_BuH, g_W2f, y, X, Dv);
}

// ---------------- chunk prefix: serial-8 / warp-KS / cross-warp hybrid -------
// Grid 128 (j = channel pair), 256 threads. Thread t covers chunks [8t, 8t+8).
__global__ void __launch_bounds__(256) chunk_prefix_hyb() {
    __shared__ float4 s_tot[8], s_ex[8];
    const int j = blockIdx.x;
    const int tid = threadIdx.x, w = tid >> 5, lane = tid & 31;
    const float2 lt0 = g_lamPow[2 * j];
    const float2 lt1 = g_lamPow[2 * j + 1];
    const float4* carry = (const float4*)g_carryf;
    float4* hinit = (float4*)g_hinitf;
    const int ct0 = tid * 8;

    float4 cr[8];
    float4 b = make_float4(0.f, 0.f, 0.f, 0.f);
    #pragma unroll
    for (int i = 0; i < 8; i++) {
        cr[i] = carry[(size_t)(ct0 + i) * 128 + j];
        b = cstep(lt0, lt1, b, cr[i]);
    }
    #pragma unroll
    for (int s = 0; s < 5; s++) {
        int d = 1 << s;
        float4 up = shfl_up4(b, d);
        float2 p0 = g_lamPow[(3 + s) * DH + 2 * j];
        float2 p1 = g_lamPow[(3 + s) * DH + 2 * j + 1];
        if (lane >= d) {
            b.x += p0.x * up.x - p0.y * up.y;
            b.y += p0.x * up.y + p0.y * up.x;
            b.z += p1.x * up.z - p1.y * up.w;
            b.w += p1.x * up.w + p1.y * up.z;
        }
    }
    if (lane == 31) s_tot[w] = b;
    __syncthreads();
    if (tid == 0) {
        float2 q0 = g_lamPow[8 * DH + 2 * j];
        float2 q1 = g_lamPow[8 * DH + 2 * j + 1];
        float4 e = make_float4(0.f, 0.f, 0.f, 0.f);
        #pragma unroll
        for (int ww = 0; ww < 8; ww++) {
            s_ex[ww] = e;
            e = cstep(q0, q1, e, s_tot[ww]);
        }
    }
    __syncthreads();
    float4 exw = s_ex[w];
    float4 prev = shfl_up4(b, 1);
    if (lane == 0) prev = make_float4(0.f, 0.f, 0.f, 0.f);
    float2 a0 = make_float2(1.f, 0.f), a1 = make_float2(1.f, 0.f);
    #pragma unroll
    for (int k = 0; k < 5; k++) {
        if ((lane >> k) & 1) {
            float2 p0 = g_lamPow[(3 + k) * DH + 2 * j];
            float2 p1 = g_lamPow[(3 + k) * DH + 2 * j + 1];
            float2 n0 = make_float2(a0.x * p0.x - a0.y * p0.y, a0.x * p0.y + a0.y * p0.x);
            float2 n1 = make_float2(a1.x * p1.x - a1.y * p1.y, a1.x * p1.y + a1.y * p1.x);
            a0 = n0; a1 = n1;
        }
    }
    float4 e;
    e.x = prev.x + a0.x * exw.x - a0.y * exw.y;
    e.y = prev.y + a0.x * exw.y + a0.y * exw.x;
    e.z = prev.z + a1.x * exw.z - a1.y * exw.w;
    e.w = prev.w + a1.x * exw.w + a1.y * exw.z;
    #pragma unroll
    for (int i = 0; i < 8; i++) {
        hinit[(size_t)(ct0 + i) * 128 + j] = e;
        e = cstep(lt0, lt1, e, cr[i]);
    }
}

// ---------------- entry ----------------
extern "C" void kernel_launch(void* const* d_in, const int* in_sizes, int n_in,
                              void* d_out, int out_size) {
    const float* x         = (const float*)d_in[0];
    const float* nu_log    = (const float*)d_in[1];
    const float* theta_log = (const float*)d_in[2];
    const float* gamma_log = (const float*)d_in[3];
    const float* B_re      = (const float*)d_in[4];
    const float* B_im      = (const float*)d_in[5];
    const float* C_re      = (const float*)d_in[6];
    const float* C_im      = (const float*)d_in[7];
    const float* Dv        = (const float*)d_in[8];
    float* y = (float*)d_out;

    cudaFuncSetAttribute(gemm1_k, cudaFuncAttributeMaxDynamicSharedMemorySize, SMEM_G);
    cudaFuncSetAttribute(gemm2_k, cudaFuncAttributeMaxDynamicSharedMemorySize, SMEM_G);

    // weights + params + x-convert in one launch
    setup_all<<<512 + (L_SEQ * DM / 4) / 256, 256>>>(
        nu_log, theta_log, gamma_log, B_re, B_im, C_re, C_im, x);

    // GEMM1 (+ fused per-chunk carry scan): BuH = x @ W1T^T
    gemm1_k<<<dim3(NW1 / 128, L_SEQ / 128), 256, SMEM_G>>>();

    chunk_prefix_hyb<<<128, 256>>>();

    // GEMM2 (+ fused apply-scan in prologue): y = (scan BuH) @ W2T^T + x*D
    gemm2_k<<<dim3(DM / 128, L_SEQ / 128), 256, SMEM_G>>>(y, x, Dv);
}